// round 9
// baseline (speedup 1.0000x reference)
#include <cuda_runtime.h>
#include <cstdint>

#define NB 4
#define NT 2048
#define ND 1024
#define NH 16
#define NHD 64
#define NM (NB*NT)   // 8192 rows

// Scratch (allocation-free rule: __device__ globals).
__device__ float g_q [NB*NH*NT*NHD];   // [B,H,T,HD]
__device__ float g_kt[NB*NH*NHD*NT];   // [B,H,HD,T]  (K projected + transposed)
__device__ float g_v [NB*NH*NT*NHD];   // [B,H,T,HD]
__device__ float g_o [NB*NH*NT*NHD];   // [B,H,T,HD] attention output

__device__ __forceinline__ unsigned f2tf(float f) {
    unsigned u;
    asm("cvt.rna.tf32.f32 %0, %1;" : "=r"(u) : "f"(f));
    return u;
}
__device__ __forceinline__ float tf32r(float f) { return __uint_as_float(f2tf(f)); }

__device__ __forceinline__ void mma_tf32(float c[4], const unsigned a[4], const unsigned b[2]) {
    asm volatile(
        "mma.sync.aligned.m16n8k8.row.col.f32.tf32.tf32.f32 "
        "{%0,%1,%2,%3}, {%4,%5,%6,%7}, {%8,%9}, {%0,%1,%2,%3};"
        : "+f"(c[0]), "+f"(c[1]), "+f"(c[2]), "+f"(c[3])
        : "r"(a[0]), "r"(a[1]), "r"(a[2]), "r"(a[3]), "r"(b[0]), "r"(b[1]));
}
__device__ __forceinline__ void mma_f(float c[4], const float a[4], const float b0, const float b1) {
    asm volatile(
        "mma.sync.aligned.m16n8k8.row.col.f32.tf32.tf32.f32 "
        "{%0,%1,%2,%3}, {%4,%5,%6,%7}, {%8,%9}, {%0,%1,%2,%3};"
        : "+f"(c[0]), "+f"(c[1]), "+f"(c[2]), "+f"(c[3])
        : "r"(__float_as_uint(a[0])), "r"(__float_as_uint(a[1])),
          "r"(__float_as_uint(a[2])), "r"(__float_as_uint(a[3])),
          "r"(__float_as_uint(b0)),   "r"(__float_as_uint(b1)));
}

// ---------------------------------------------------------------------------
// Tensor-core tf32 GEMM (verbatim from passing R3/R5-R8): C = A@W^T + bias.
// ---------------------------------------------------------------------------
template<int AMODE, int OMODE>
__global__ __launch_bounds__(256)
void gemm_tc(const float* __restrict__ A, const float* __restrict__ W,
             const float* __restrict__ bias, float* __restrict__ Cout)
{
    extern __shared__ unsigned sh[];
    unsigned* As = sh;           // 2 bufs x 4096 u32
    unsigned* Ws = sh + 8192;

    const int tid  = threadIdx.x;
    const int lane = tid & 31;
    const int warp = tid >> 5;
    const int wm   = warp & 1;
    const int wn   = warp >> 1;
    const int bm   = blockIdx.y * 128;
    const int bn   = blockIdx.x * 128;

    float acc[4][4][4];
#pragma unroll
    for (int mi = 0; mi < 4; mi++)
#pragma unroll
        for (int nj = 0; nj < 4; nj++)
#pragma unroll
            for (int r = 0; r < 4; r++) acc[mi][nj][r] = 0.f;

    float4 ar[4], wr[4];

    auto ldg = [&](int s) {
#pragma unroll
        for (int l = 0; l < 4; l++) {
            int idx = l * 256 + tid;
            int row = idx >> 3;
            int kq  = idx & 7;
            int kg  = s * 32 + kq * 4;
            if (AMODE == 0) {
                ar[l] = *(const float4*)(A + (size_t)(bm + row) * ND + kg);
            } else {
                int m  = bm + row;
                int b_ = m >> 11, t_ = m & (NT - 1);
                int h_ = kg >> 6, hd = kg & 63;
                ar[l] = *(const float4*)(A + (((size_t)(b_ * NH + h_) * NT + t_) * NHD + hd));
            }
            wr[l] = *(const float4*)(W + (size_t)(bn + row) * ND + kg);
        }
    };

    auto sts = [&](int buf) {
        unsigned* ab = As + buf * 4096;
        unsigned* wb = Ws + buf * 4096;
#pragma unroll
        for (int l = 0; l < 4; l++) {
            int idx = l * 256 + tid;
            int row = idx >> 3;
            int kq  = idx & 7;
            {
                unsigned* p = ab + (((row >> 4) * 4 + (kq >> 1)) << 7);
                int reg = ((kq & 1) << 1) + ((row >> 3) & 1);
                int lb  = (row & 7) * 4;
                p[(lb + 0) * 4 + reg] = f2tf(ar[l].x);
                p[(lb + 1) * 4 + reg] = f2tf(ar[l].y);
                p[(lb + 2) * 4 + reg] = f2tf(ar[l].z);
                p[(lb + 3) * 4 + reg] = f2tf(ar[l].w);
            }
            {
                unsigned* p = wb + (((row >> 3) * 4 + (kq >> 1)) << 6);
                int reg = (kq & 1);
                int lb  = (row & 7) * 4;
                p[(lb + 0) * 2 + reg] = f2tf(wr[l].x);
                p[(lb + 1) * 2 + reg] = f2tf(wr[l].y);
                p[(lb + 2) * 2 + reg] = f2tf(wr[l].z);
                p[(lb + 3) * 2 + reg] = f2tf(wr[l].w);
            }
        }
    };

    auto compute = [&](int buf) {
        const unsigned* ab = As + buf * 4096;
        const unsigned* wb = Ws + buf * 4096;
#pragma unroll
        for (int kt = 0; kt < 4; kt++) {
            unsigned af[4][4];
#pragma unroll
            for (int mi = 0; mi < 4; mi++) {
                uint4 t = *(const uint4*)(ab + ((((wm * 4 + mi) * 4 + kt)) << 7) + (lane << 2));
                af[mi][0] = t.x; af[mi][1] = t.y; af[mi][2] = t.z; af[mi][3] = t.w;
            }
            unsigned bf[4][2];
#pragma unroll
            for (int nj = 0; nj < 4; nj++) {
                uint2 t = *(const uint2*)(wb + ((((wn * 4 + nj) * 4 + kt)) << 6) + (lane << 1));
                bf[nj][0] = t.x; bf[nj][1] = t.y;
            }
#pragma unroll
            for (int mi = 0; mi < 4; mi++)
#pragma unroll
                for (int nj = 0; nj < 4; nj++)
                    mma_tf32(acc[mi][nj], af[mi], bf[nj]);
        }
    };

    ldg(0);
    sts(0);
    __syncthreads();
    for (int s = 0; s < 32; s++) {
        int buf = s & 1;
        if (s < 31) ldg(s + 1);
        compute(buf);
        if (s < 31) sts(buf ^ 1);
        __syncthreads();
    }

#pragma unroll
    for (int nj = 0; nj < 4; nj++) {
        int col = bn + (wn * 4 + nj) * 8 + (lane & 3) * 2;
        float b0 = bias[col], b1 = bias[col + 1];
#pragma unroll
        for (int mi = 0; mi < 4; mi++) {
            int row = bm + (wm * 4 + mi) * 16 + (lane >> 2);
            float v00 = acc[mi][nj][0] + b0, v01 = acc[mi][nj][1] + b1;
            float v10 = acc[mi][nj][2] + b0, v11 = acc[mi][nj][3] + b1;
            if (OMODE == 2) {
                *(float2*)(Cout + (size_t)row * ND + col)       = make_float2(v00, v01);
                *(float2*)(Cout + (size_t)(row + 8) * ND + col) = make_float2(v10, v11);
            } else if (OMODE == 0) {
                int b_ = row >> 11, t_ = row & (NT - 1);
                int h_ = col >> 6, hd = col & 63;
                float* p = Cout + (((size_t)(b_ * NH + h_) * NT + t_) * NHD + hd);
                *(float2*)p             = make_float2(v00, v01);
                *(float2*)(p + 8 * NHD) = make_float2(v10, v11);
            } else { // OMODE 1: [B,H,HD,T]
                int b_ = row >> 11, t_ = row & (NT - 1);
                int h_ = col >> 6, hd = col & 63;
                float* p = Cout + (((size_t)(b_ * NH + h_) * NHD + hd) * NT + t_);
                p[0]      = v00;
                p[NT]     = v01;
                p[8]      = v10;
                p[NT + 8] = v11;
            }
        }
    }
}

// ---------------------------------------------------------------------------
// Flash attention v5: fragment-order staging + 2 m-tiles per warp.
// 128 threads = 4 warps; CTA = 128 queries; warp owns 32 rows (m-tiles
// warp*2, warp*2+1). smem identical to R8 (112 KB) -> 2 CTAs/SM.
// Math bit-identical to R7/R8 (rel_err must stay 6.511e-4).
// smem (u32): QH[0,8192) QL[8192,16384) K[16384,24576) V[24576,28672)
// ---------------------------------------------------------------------------
__global__ __launch_bounds__(128, 2)
void attn_mma(const float* __restrict__ qp, const float* __restrict__ ktp,
              const float* __restrict__ vp, float* __restrict__ ao)
{
    extern __shared__ unsigned smu[];

    const int tid  = threadIdx.x;
    const int lane = tid & 31;
    const int warp = tid >> 5;           // 0..3
    const int r    = lane >> 2;          // 0..7
    const int g    = lane & 3;           // 0..3
    const int bh   = blockIdx.y;
    const int q0   = blockIdx.x * 128;

    const float* qb = qp  + ((size_t)bh * NT + q0) * NHD;
    const float* kb = ktp + (size_t)bh * NHD * NT;
    const float* vb = vp  + (size_t)bh * NT * NHD;

    // ---- Stage Q once in A-frag order (hi/lo). 2048 float4, 16 iters. ----
#pragma unroll
    for (int i = 0; i < 16; i++) {
        int idx = i * 128 + tid;
        int uu = idx & 31, blk = idx >> 5;          // blk 0..63
        int qrow = (uu >> 2) + (blk & 15) * 8;      // 0..127
        int f4   = (uu & 3) + (blk >> 4) * 4;       // 0..15
        float4 x = *(const float4*)(qb + qrow * NHD + f4 * 4);
        float xe[4] = {x.x, x.y, x.z, x.w};
        int mt = qrow >> 4;
        int lb = (qrow & 7) * 4;
        int rr = (qrow >> 3) & 1;
#pragma unroll
        for (int e = 0; e < 4; e++) {
            int hd = f4 * 4 + e;
            int ad = ((mt * 8 + (hd >> 3)) * 128) + (lb + (hd & 3)) * 4
                     + ((hd >> 2) & 1) * 2 + rr;
            float h = tf32r(xe[e]);
            smu[ad]        = __float_as_uint(h);
            smu[8192 + ad] = f2tf(xe[e] - h);
        }
    }

    float o[2][8][4];
    float m0[2], m1[2], l0[2], l1[2];
#pragma unroll
    for (int mt = 0; mt < 2; mt++) {
        m0[mt] = -1e30f; m1[mt] = -1e30f; l0[mt] = 0.f; l1[mt] = 0.f;
#pragma unroll
        for (int nt = 0; nt < 8; nt++)
#pragma unroll
            for (int c = 0; c < 4; c++) o[mt][nt][c] = 0.f;
    }

    for (int t0 = 0; t0 < NT; t0 += 64) {
        __syncthreads();   // prev compute done before restaging (covers Q on iter 0)
        // ---- Stage K (hi/lo interleaved) and V in B-frag order. 8 iters. ----
#pragma unroll
        for (int i = 0; i < 8; i++) {
            int idx = i * 128 + tid;
            int uu = idx & 31, blk = idx >> 5;      // blk 0..31
            int row = (uu >> 2) + (blk & 7) * 8;    // 0..63
            int f4  = (uu & 3) + (blk >> 3) * 4;    // 0..15
            {   // K: row = hd, f4 indexes keys
                float4 x = *(const float4*)(kb + (size_t)row * NT + t0 + f4 * 4);
                float xe[4] = {x.x, x.y, x.z, x.w};
                int kt = row >> 3;
                int reg = (row >> 2) & 1;
                int lh = row & 3;
#pragma unroll
                for (int e = 0; e < 4; e++) {
                    int key = f4 * 4 + e;
                    int ad = 16384 + (((key >> 3) * 8 + kt) * 128)
                             + ((key & 7) * 4 + lh) * 4 + reg;
                    float h = tf32r(xe[e]);
                    smu[ad]     = __float_as_uint(h);
                    smu[ad + 2] = f2tf(xe[e] - h);
                }
            }
            {   // V: row = key, f4 indexes hd
                float4 y = *(const float4*)(vb + (size_t)(t0 + row) * NHD + f4 * 4);
                float ye[4] = {y.x, y.y, y.z, y.w};
                int kt = row >> 3;
                int reg = (row >> 2) & 1;
                int lk = row & 3;
#pragma unroll
                for (int e = 0; e < 4; e++) {
                    int hd = f4 * 4 + e;
                    int ad = 24576 + (((hd >> 3) * 8 + kt) * 64)
                             + ((hd & 7) * 4 + lk) * 2 + reg;
                    smu[ad] = f2tf(ye[e]);
                }
            }
        }
        __syncthreads();

        // ---- S = Q K^T : 2 m-tiles share each K frag load ----
        float s[2][8][4];
#pragma unroll
        for (int mt = 0; mt < 2; mt++)
#pragma unroll
            for (int nt = 0; nt < 8; nt++)
#pragma unroll
                for (int c = 0; c < 4; c++) s[mt][nt][c] = 0.f;

#pragma unroll
        for (int kt = 0; kt < 8; kt++) {
            float ah[2][4], al[2][4];
#pragma unroll
            for (int mt = 0; mt < 2; mt++) {
                uint4 qh4 = *(const uint4*)(smu + ((warp * 2 + mt) * 8 + kt) * 128 + lane * 4);
                uint4 ql4 = *(const uint4*)(smu + 8192 + ((warp * 2 + mt) * 8 + kt) * 128 + lane * 4);
                ah[mt][0] = __uint_as_float(qh4.x); ah[mt][1] = __uint_as_float(qh4.y);
                ah[mt][2] = __uint_as_float(qh4.z); ah[mt][3] = __uint_as_float(qh4.w);
                al[mt][0] = __uint_as_float(ql4.x); al[mt][1] = __uint_as_float(ql4.y);
                al[mt][2] = __uint_as_float(ql4.z); al[mt][3] = __uint_as_float(ql4.w);
            }
#pragma unroll
            for (int half = 0; half < 2; half++) {
                uint4 kk[4];
#pragma unroll
                for (int j = 0; j < 4; j++)
                    kk[j] = *(const uint4*)(smu + 16384
                              + (((half * 4 + j) * 8 + kt) * 128) + lane * 4);
#pragma unroll
                for (int mt = 0; mt < 2; mt++)
#pragma unroll
                    for (int j = 0; j < 4; j++)
                        mma_f(s[mt][half*4+j], ah[mt],
                              __uint_as_float(kk[j].x), __uint_as_float(kk[j].y));
#pragma unroll
                for (int mt = 0; mt < 2; mt++)
#pragma unroll
                    for (int j = 0; j < 4; j++)
                        mma_f(s[mt][half*4+j], ah[mt],
                              __uint_as_float(kk[j].z), __uint_as_float(kk[j].w));
#pragma unroll
                for (int mt = 0; mt < 2; mt++)
#pragma unroll
                    for (int j = 0; j < 4; j++)
                        mma_f(s[mt][half*4+j], al[mt],
                              __uint_as_float(kk[j].x), __uint_as_float(kk[j].y));
            }
        }

        // ---- online softmax per m-tile (rows r, r+8; quad-wide) ----
#pragma unroll
        for (int mt = 0; mt < 2; mt++) {
            float mx0 = -1e30f, mx1 = -1e30f;
#pragma unroll
            for (int nt = 0; nt < 8; nt++) {
                s[mt][nt][0] *= 0.125f; s[mt][nt][1] *= 0.125f;
                s[mt][nt][2] *= 0.125f; s[mt][nt][3] *= 0.125f;
                mx0 = fmaxf(mx0, fmaxf(s[mt][nt][0], s[mt][nt][1]));
                mx1 = fmaxf(mx1, fmaxf(s[mt][nt][2], s[mt][nt][3]));
            }
            mx0 = fmaxf(mx0, __shfl_xor_sync(0xffffffffu, mx0, 1));
            mx0 = fmaxf(mx0, __shfl_xor_sync(0xffffffffu, mx0, 2));
            mx1 = fmaxf(mx1, __shfl_xor_sync(0xffffffffu, mx1, 1));
            mx1 = fmaxf(mx1, __shfl_xor_sync(0xffffffffu, mx1, 2));

            float mn0 = fmaxf(m0[mt], mx0), mn1 = fmaxf(m1[mt], mx1);
            float c0 = __expf(m0[mt] - mn0), c1 = __expf(m1[mt] - mn1);
            m0[mt] = mn0; m1[mt] = mn1;

            float rs0 = 0.f, rs1 = 0.f;
#pragma unroll
            for (int nt = 0; nt < 8; nt++) {
                float p;
                p = tf32r(__expf(s[mt][nt][0] - mn0)); s[mt][nt][0] = p; rs0 += p;
                p = tf32r(__expf(s[mt][nt][1] - mn0)); s[mt][nt][1] = p; rs0 += p;
                p = tf32r(__expf(s[mt][nt][2] - mn1)); s[mt][nt][2] = p; rs1 += p;
                p = tf32r(__expf(s[mt][nt][3] - mn1)); s[mt][nt][3] = p; rs1 += p;
            }
            rs0 += __shfl_xor_sync(0xffffffffu, rs0, 1);
            rs0 += __shfl_xor_sync(0xffffffffu, rs0, 2);
            rs1 += __shfl_xor_sync(0xffffffffu, rs1, 1);
            rs1 += __shfl_xor_sync(0xffffffffu, rs1, 2);
            l0[mt] = l0[mt] * c0 + rs0;
            l1[mt] = l1[mt] * c1 + rs1;
#pragma unroll
            for (int nt = 0; nt < 8; nt++) {
                o[mt][nt][0] *= c0; o[mt][nt][1] *= c0;
                o[mt][nt][2] *= c1; o[mt][nt][3] *= c1;
            }
        }

        // ---- O += P V : V frag loads shared by both m-tiles ----
        const int src1 = (lane & ~3) | (g >> 1);
        const int src2 = src1 + 2;
        const bool odd = (g & 1) != 0;
#pragma unroll
        for (int kt = 0; kt < 8; kt++) {
            float a[2][4];
#pragma unroll
            for (int mt = 0; mt < 2; mt++) {
                float x0 = __shfl_sync(0xffffffffu, s[mt][kt][0], src1);
                float x1 = __shfl_sync(0xffffffffu, s[mt][kt][1], src1);
                float y0 = __shfl_sync(0xffffffffu, s[mt][kt][2], src1);
                float y1 = __shfl_sync(0xffffffffu, s[mt][kt][3], src1);
                float z0 = __shfl_sync(0xffffffffu, s[mt][kt][0], src2);
                float z1 = __shfl_sync(0xffffffffu, s[mt][kt][1], src2);
                float w0 = __shfl_sync(0xffffffffu, s[mt][kt][2], src2);
                float w1 = __shfl_sync(0xffffffffu, s[mt][kt][3], src2);
                a[mt][0] = odd ? x1 : x0;
                a[mt][1] = odd ? y1 : y0;
                a[mt][2] = odd ? z1 : z0;
                a[mt][3] = odd ? w1 : w0;
            }
#pragma unroll
            for (int nt = 0; nt < 8; nt++) {
                uint2 vv = *(const uint2*)(smu + 24576 + ((nt * 8 + kt) * 64) + lane * 2);
                float v0 = __uint_as_float(vv.x), v1 = __uint_as_float(vv.y);
                mma_f(o[0][nt], a[0], v0, v1);
                mma_f(o[1][nt], a[1], v0, v1);
            }
        }
    }

    // ---- normalize + store [B,H,T,HD] ----
#pragma unroll
    for (int mt = 0; mt < 2; mt++) {
        float inv0 = 1.f / l0[mt], inv1 = 1.f / l1[mt];
        float* ob = ao + ((size_t)bh * NT + q0 + (warp * 2 + mt) * 16) * NHD;
#pragma unroll
        for (int nt = 0; nt < 8; nt++) {
            int col = nt * 8 + 2 * g;
            *(float2*)(ob + (size_t)r * NHD + col) =
                make_float2(o[mt][nt][0] * inv0, o[mt][nt][1] * inv0);
            *(float2*)(ob + (size_t)(r + 8) * NHD + col) =
                make_float2(o[mt][nt][2] * inv1, o[mt][nt][3] * inv1);
        }
    }
}

// ---------------------------------------------------------------------------
extern "C" void kernel_launch(void* const* d_in, const int* in_sizes, int n_in,
                              void* d_out, int out_size)
{
    const float* q  = (const float*)d_in[0];
    const float* k  = (const float*)d_in[1];
    const float* v  = (const float*)d_in[2];
    const float* Wq = (const float*)d_in[3];
    const float* bq = (const float*)d_in[4];
    const float* Wk = (const float*)d_in[5];
    const float* bk = (const float*)d_in[6];
    const float* Wv = (const float*)d_in[7];
    const float* bv = (const float*)d_in[8];
    const float* Wo = (const float*)d_in[9];
    const float* bo = (const float*)d_in[10];
    float* out = (float*)d_out;

    float *pq, *pkt, *pv, *po;
    cudaGetSymbolAddress((void**)&pq,  g_q);
    cudaGetSymbolAddress((void**)&pkt, g_kt);
    cudaGetSymbolAddress((void**)&pv,  g_v);
    cudaGetSymbolAddress((void**)&po,  g_o);

    const int gemm_smem = 65536;
    cudaFuncSetAttribute(gemm_tc<0,0>, cudaFuncAttributeMaxDynamicSharedMemorySize, gemm_smem);
    cudaFuncSetAttribute(gemm_tc<0,1>, cudaFuncAttributeMaxDynamicSharedMemorySize, gemm_smem);
    cudaFuncSetAttribute(gemm_tc<1,2>, cudaFuncAttributeMaxDynamicSharedMemorySize, gemm_smem);

    dim3 gg(ND / 128, NM / 128);   // (8, 64)

    gemm_tc<0, 0><<<gg, 256, gemm_smem>>>(q, Wq, bq, pq);
    gemm_tc<0, 1><<<gg, 256, gemm_smem>>>(k, Wk, bk, pkt);   // K proj + transpose fused
    gemm_tc<0, 0><<<gg, 256, gemm_smem>>>(v, Wv, bv, pv);

    const int attn_smem = 28672 * 4;   // 114,688 B -> 2 CTAs/SM
    cudaFuncSetAttribute(attn_mma, cudaFuncAttributeMaxDynamicSharedMemorySize, attn_smem);
    attn_mma<<<dim3(NT / 128, NB * NH), 128, attn_smem>>>(pq, pkt, pv, po);

    gemm_tc<1, 2><<<gg, 256, gemm_smem>>>(po, Wo, bo, out);
}